// round 10
// baseline (speedup 1.0000x reference)
#include <cuda_runtime.h>
#include <cuda_fp16.h>
#include <math.h>

#define N_NODES 100000
#define N_EDGES 1600000
#define QUART_E (N_EDGES / 4)
#define FULL 0xffffffffu

// ---------------- scratch (static device globals; no allocations) ----------
// Edge record: {src | j<<20, dst, half2(b_j, b_j5), half2(b_j1, b_j6)}
__device__ int4   g_edge[N_EDGES];
__device__ float  g_deg[N_NODES];
__device__ float4 g_agg[N_NODES * 4];            // [N][16]; zero at call entry/exit
__device__ float4 g_h1[N_NODES * 4];             // hidden ping
__device__ float4 g_h2[N_NODES * 4];             // hidden pong
__device__ uint2  g_xwh[N_NODES * 100];          // [N][25][16] fp16 XW (80MB)

// ---------------- kernels --------------------------------------------------

__global__ void zero_deg_kernel() {
    int i = blockIdx.x * blockDim.x + threadIdx.x;
    if (i < N_NODES) g_deg[i] = 0.f;
}

__global__ void prep_kernel(const float2* __restrict__ attr,
                            const int* __restrict__ src,
                            const int* __restrict__ dst) {
    int e = blockIdx.x * blockDim.x + threadIdx.x;
    if (e >= N_EDGES) return;
    float2 a = attr[e];
    float v0 = a.x * 4.f, v1 = a.y * 4.f;
    float k0f = fminf(fmaxf(floorf(v0), 0.f), 3.f);
    float k1f = fminf(fmaxf(floorf(v1), 0.f), 3.f);
    float f0 = v0 - k0f, f1 = v1 - k1f;
    int k0 = (int)k0f, k1 = (int)k1f;
    float bj  = (1.f - f0) * (1.f - f1);
    float bj5 = (1.f - f0) * f1;
    float bj1 = f0 * (1.f - f1);
    float bj6 = f0 * f1;
    int j = k0 + 5 * k1;
    int d = dst[e];
    __half2 p0 = __floats2half2_rn(bj,  bj5);
    __half2 p1 = __floats2half2_rn(bj1, bj6);
    int4 rec;
    rec.x = src[e] | (j << 20);
    rec.y = d;
    rec.z = *reinterpret_cast<int*>(&p0);
    rec.w = *reinterpret_cast<int*>(&p1);
    g_edge[e] = rec;
    atomicAdd(&g_deg[d], 1.f);
}

__device__ __forceinline__ void red_add_v4(float* p, float4 v) {
    asm volatile("red.global.add.v4.f32 [%0], {%1,%2,%3,%4};"
                 :: "l"(p), "f"(v.x), "f"(v.y), "f"(v.z), "f"(v.w) : "memory");
}

__device__ __forceinline__ float2 h2f2(unsigned u) {
    __half2 h = *reinterpret_cast<__half2*>(&u);
    return __half22float2(h);
}

// Layer 1 edge kernel: in=2, 4 threads/edge, FOUR edges per thread (MLP=8).
__global__ void edge1_kernel(const float2* __restrict__ x,
                             const float* __restrict__ W1) {
    __shared__ uint4 Wsh[100];                   // [25][4] fp16
    if (threadIdx.x < 100) {
        int w = threadIdx.x >> 2, l = threadIdx.x & 3;
        const float4* Wv = (const float4*)W1;    // [25][2][4] float4
        float4 a0 = Wv[w * 8 + l];
        float4 a1 = Wv[w * 8 + 4 + l];
        __half2 p0 = __floats2half2_rn(a0.x, a0.y);
        __half2 p1 = __floats2half2_rn(a0.z, a0.w);
        __half2 p2 = __floats2half2_rn(a1.x, a1.y);
        __half2 p3 = __floats2half2_rn(a1.z, a1.w);
        uint4 u;
        u.x = *reinterpret_cast<unsigned*>(&p0);
        u.y = *reinterpret_cast<unsigned*>(&p1);
        u.z = *reinterpret_cast<unsigned*>(&p2);
        u.w = *reinterpret_cast<unsigned*>(&p3);
        Wsh[w * 4 + l] = u;
    }
    __syncthreads();
    int t = blockIdx.x * blockDim.x + threadIdx.x;   // QUART_E*4 threads
    int e0 = t >> 2;
    int l = threadIdx.x & 3;
    const int woff[4] = {0, 5, 1, 6};
    // front-batch all 4 edge records and x gathers (MLP=8)
    int4 rec[4];
    float2 xv[4];
#pragma unroll
    for (int i = 0; i < 4; i++) rec[i] = g_edge[e0 + i * QUART_E];
#pragma unroll
    for (int i = 0; i < 4; i++) xv[i] = x[rec[i].x & 0xFFFFF];
#pragma unroll
    for (int i = 0; i < 4; i++) {
        int j = rec[i].x >> 20;
        float2 b0 = h2f2(rec[i].z), b1 = h2f2(rec[i].w);
        float bs[4] = {b0.x, b0.y, b1.x, b1.y};
        float4 acc = make_float4(0.f, 0.f, 0.f, 0.f);
#pragma unroll
        for (int q = 0; q < 4; q++) {
            uint4 wv = Wsh[(j + woff[q]) * 4 + l];
            float2 w00 = h2f2(wv.x), w01 = h2f2(wv.y);
            float2 w10 = h2f2(wv.z), w11 = h2f2(wv.w);
            float c0 = bs[q] * xv[i].x, c1 = bs[q] * xv[i].y;
            acc.x += c0 * w00.x + c1 * w10.x;
            acc.y += c0 * w00.y + c1 * w10.y;
            acc.z += c0 * w01.x + c1 * w11.x;
            acc.w += c0 * w01.y + c1 * w11.y;
        }
        red_add_v4((float*)&g_agg[(size_t)rec[i].y * 4 + l], acc);
    }
}

// XW precompute: 128 threads, 100 active as (k,o4), fp16 output.
__global__ void xw_kernel(const float4* __restrict__ hin,
                          const float* __restrict__ W) {
    __shared__ float4 hs[400];                   // 100 nodes x 16 floats
    int t = threadIdx.x;
    int n0 = blockIdx.x * 100;
    int k = t >> 2, o4 = t & 3;
    float4 wc[16];
    if (t < 100) {
        const float4* Wv = (const float4*)W;     // [25][16][4]
#pragma unroll
        for (int i = 0; i < 16; i++) wc[i] = Wv[(k * 16 + i) * 4 + o4];
    }
    for (int j = t; j < 400; j += blockDim.x) hs[j] = hin[n0 * 4 + j];
    __syncthreads();
    if (t >= 100) return;
    const float* hsf = (const float*)hs;
    for (int n = 0; n < 100; n++) {
        float4 a = make_float4(0.f, 0.f, 0.f, 0.f);
#pragma unroll
        for (int i = 0; i < 16; i++) {
            float hv = hsf[n * 16 + i];
            a.x += hv * wc[i].x; a.y += hv * wc[i].y;
            a.z += hv * wc[i].z; a.w += hv * wc[i].w;
        }
        __half2 h0 = __floats2half2_rn(a.x, a.y);
        __half2 h1 = __floats2half2_rn(a.z, a.w);
        uint2 u;
        u.x = *reinterpret_cast<unsigned*>(&h0);
        u.y = *reinterpret_cast<unsigned*>(&h1);
        g_xwh[((size_t)(n0 + n) * 25 + k) * 4 + o4] = u;
    }
}

// Edge gather for layers 2/3: 4 threads/edge, FOUR edges/thread (MLP 8-12).
__global__ void edge_gather_kernel() {
    int t = blockIdx.x * blockDim.x + threadIdx.x;
    int e0 = t >> 2;
    int l = threadIdx.x & 3;
    int4 rec[4];
#pragma unroll
    for (int i = 0; i < 4; i++) rec[i] = g_edge[e0 + i * QUART_E];
    // front-batch all 8 tap-pair loads (MLP=8 gathers + 4 recs)
    uint4 v1[4], v2[4];
#pragma unroll
    for (int i = 0; i < 4; i++) {
        int s = rec[i].x & 0xFFFFF;
        int j = rec[i].x >> 20;
        const char* base = (const char*)g_xwh + (size_t)s * 800 + l * 16;
        v1[i] = *reinterpret_cast<const uint4*>(base + j * 32);
        v2[i] = *reinterpret_cast<const uint4*>(base + (j + 5) * 32);
    }
#pragma unroll
    for (int i = 0; i < 4; i++) {
        float2 b0 = h2f2(rec[i].z), b1 = h2f2(rec[i].w);
        float cA = (l & 2) ? b1.x : b0.x;
        float cB = (l & 2) ? b1.y : b0.y;
        float acc[8];
        const unsigned* u1 = reinterpret_cast<const unsigned*>(&v1[i]);
        const unsigned* u2 = reinterpret_cast<const unsigned*>(&v2[i]);
#pragma unroll
        for (int p = 0; p < 4; p++) {
            float2 f1 = h2f2(u1[p]);
            float2 f2 = h2f2(u2[p]);
            acc[2 * p]     = cA * f1.x + cB * f2.x;
            acc[2 * p + 1] = cA * f1.y + cB * f2.y;
        }
#pragma unroll
        for (int p = 0; p < 8; p++)
            acc[p] += __shfl_xor_sync(FULL, acc[p], 2);
        float* ap = (float*)g_agg + (size_t)rec[i].y * 16 + ((l & 1) << 3) + ((l & 2) << 1);
        float4 out = (l & 2) ? make_float4(acc[4], acc[5], acc[6], acc[7])
                             : make_float4(acc[0], acc[1], acc[2], acc[3]);
        red_add_v4(ap, out);
    }
}

// Node update, layer 1 (root: 2x16): h = relu(agg/deg + x@root + b); zero agg.
__global__ void node1_kernel(const float2* __restrict__ x,
                             const float* __restrict__ root,
                             const float* __restrict__ bias,
                             float4* __restrict__ hout) {
    __shared__ float4 rsh[8];
    __shared__ float4 bsh[4];
    if (threadIdx.x < 8)  rsh[threadIdx.x] = ((const float4*)root)[threadIdx.x];
    if (threadIdx.x < 4)  bsh[threadIdx.x] = ((const float4*)bias)[threadIdx.x];
    __syncthreads();
    int t = blockIdx.x * blockDim.x + threadIdx.x;
    int n = t >> 2;
    if (n >= N_NODES) return;
    int l = t & 3;
    float4 a = g_agg[(size_t)n * 4 + l];
    float di = 1.f / fmaxf(g_deg[n], 1.f);
    float2 xv = x[n];
    float4 r0 = rsh[l], r1 = rsh[4 + l], bb = bsh[l];
    float4 o;
    o.x = fmaxf(bb.x + a.x * di + xv.x * r0.x + xv.y * r1.x, 0.f);
    o.y = fmaxf(bb.y + a.y * di + xv.x * r0.y + xv.y * r1.y, 0.f);
    o.z = fmaxf(bb.z + a.z * di + xv.x * r0.z + xv.y * r1.z, 0.f);
    o.w = fmaxf(bb.w + a.w * di + xv.x * r0.w + xv.y * r1.w, 0.f);
    hout[(size_t)n * 4 + l] = o;
    g_agg[(size_t)n * 4 + l] = make_float4(0.f, 0.f, 0.f, 0.f);
}

// Node update, 16-channel root; 4 threads/node.
__global__ void node16_kernel(const float4* __restrict__ hin,
                              const float* __restrict__ root,
                              const float* __restrict__ bias,
                              float4* __restrict__ hout) {
    __shared__ float4 rsh[64];                   // [16][4]
    __shared__ float4 bsh[4];
    for (int j = threadIdx.x; j < 64; j += blockDim.x)
        rsh[j] = ((const float4*)root)[j];
    if (threadIdx.x < 4) bsh[threadIdx.x] = ((const float4*)bias)[threadIdx.x];
    __syncthreads();
    int t = blockIdx.x * blockDim.x + threadIdx.x;
    int n = t >> 2;
    if (n >= N_NODES) return;
    int l = t & 3;
    float4 a = g_agg[(size_t)n * 4 + l];
    float di = 1.f / fmaxf(g_deg[n], 1.f);
    float4 acc = bsh[l];
    acc.x += a.x * di; acc.y += a.y * di; acc.z += a.z * di; acc.w += a.w * di;
    const float* h = (const float*)(hin + (size_t)n * 4);
#pragma unroll
    for (int i = 0; i < 16; i++) {
        float hv = h[i];
        float4 r = rsh[i * 4 + l];
        acc.x += hv * r.x; acc.y += hv * r.y; acc.z += hv * r.z; acc.w += hv * r.w;
    }
    acc.x = fmaxf(acc.x, 0.f); acc.y = fmaxf(acc.y, 0.f);
    acc.z = fmaxf(acc.z, 0.f); acc.w = fmaxf(acc.w, 0.f);
    hout[(size_t)n * 4 + l] = acc;
    g_agg[(size_t)n * 4 + l] = make_float4(0.f, 0.f, 0.f, 0.f);
}

// Layer-3 node update fused with fc head: relu(...) -> dot fc_w -> sigmoid.
__global__ void node16_final_kernel(const float4* __restrict__ hin,
                                    const float* __restrict__ root,
                                    const float* __restrict__ bias,
                                    const float* __restrict__ fcw,
                                    const float* __restrict__ fcb,
                                    float* __restrict__ out) {
    __shared__ float4 rsh[64];
    __shared__ float4 bsh[4];
    __shared__ float4 wsh[4];
    for (int j = threadIdx.x; j < 64; j += blockDim.x)
        rsh[j] = ((const float4*)root)[j];
    if (threadIdx.x < 4) {
        bsh[threadIdx.x] = ((const float4*)bias)[threadIdx.x];
        wsh[threadIdx.x] = ((const float4*)fcw)[threadIdx.x];
    }
    __syncthreads();
    int t = blockIdx.x * blockDim.x + threadIdx.x;
    int n = t >> 2;
    if (n >= N_NODES) return;
    int l = t & 3;
    float4 a = g_agg[(size_t)n * 4 + l];
    float di = 1.f / fmaxf(g_deg[n], 1.f);
    float4 acc = bsh[l];
    acc.x += a.x * di; acc.y += a.y * di; acc.z += a.z * di; acc.w += a.w * di;
    const float* h = (const float*)(hin + (size_t)n * 4);
#pragma unroll
    for (int i = 0; i < 16; i++) {
        float hv = h[i];
        float4 r = rsh[i * 4 + l];
        acc.x += hv * r.x; acc.y += hv * r.y; acc.z += hv * r.z; acc.w += hv * r.w;
    }
    acc.x = fmaxf(acc.x, 0.f); acc.y = fmaxf(acc.y, 0.f);
    acc.z = fmaxf(acc.z, 0.f); acc.w = fmaxf(acc.w, 0.f);
    g_agg[(size_t)n * 4 + l] = make_float4(0.f, 0.f, 0.f, 0.f);
    float4 wv = wsh[l];
    float z = acc.x * wv.x + acc.y * wv.y + acc.z * wv.z + acc.w * wv.w;
    z += __shfl_xor_sync(FULL, z, 1);
    z += __shfl_xor_sync(FULL, z, 2);
    if (l == 0) out[n] = 1.f / (1.f + expf(-(z + fcb[0])));
}

// ---------------- launch ---------------------------------------------------

extern "C" void kernel_launch(void* const* d_in, const int* in_sizes, int n_in,
                              void* d_out, int out_size) {
    const float2* x     = (const float2*)d_in[0];
    const int*    ei    = (const int*)d_in[1];
    const float2* attr  = (const float2*)d_in[2];
    const float*  W1    = (const float*)d_in[3];
    const float*  root1 = (const float*)d_in[4];
    const float*  b1    = (const float*)d_in[5];
    const float*  W2    = (const float*)d_in[6];
    const float*  root2 = (const float*)d_in[7];
    const float*  b2    = (const float*)d_in[8];
    const float*  W3    = (const float*)d_in[9];
    const float*  root3 = (const float*)d_in[10];
    const float*  b3    = (const float*)d_in[11];
    const float*  fcw   = (const float*)d_in[12];
    const float*  fcb   = (const float*)d_in[13];
    const int* src = ei;
    const int* dst = ei + N_EDGES;

    float4 *h1, *h2;
    cudaGetSymbolAddress((void**)&h1, g_h1);
    cudaGetSymbolAddress((void**)&h2, g_h2);

    const int TB = 256;
    int gEdge  = (N_EDGES + TB - 1) / TB;
    int gEdge4 = (QUART_E * 4) / TB;             // 4 edges/thread: 6250
    int gNode4 = (N_NODES * 4 + TB - 1) / TB;
    int gNode  = (N_NODES + TB - 1) / TB;

    zero_deg_kernel<<<gNode, TB>>>();
    prep_kernel<<<gEdge, TB>>>(attr, src, dst);

    // layer 1 (in=2)
    edge1_kernel<<<gEdge4, TB>>>(x, W1);
    node1_kernel<<<gNode4, TB>>>(x, root1, b1, h1);

    // layer 2
    xw_kernel<<<N_NODES / 100, 128>>>(h1, W2);
    edge_gather_kernel<<<gEdge4, TB>>>();
    node16_kernel<<<gNode4, TB>>>(h1, root2, b2, h2);

    // layer 3 (node update fused with fc head)
    xw_kernel<<<N_NODES / 100, 128>>>(h2, W3);
    edge_gather_kernel<<<gEdge4, TB>>>();
    node16_final_kernel<<<gNode4, TB>>>(h2, root3, b3, fcw, fcb, (float*)d_out);
}

// round 11
// speedup vs baseline: 1.0244x; 1.0244x over previous
#include <cuda_runtime.h>
#include <cuda_fp16.h>
#include <math.h>

#define N_NODES 100000
#define N_EDGES 1600000
#define HALF_E  (N_EDGES / 2)
#define FULL 0xffffffffu

// ---------------- scratch (static device globals; no allocations) ----------
// Edge record: {src | j<<20, dst, half2(b_j, b_j5), half2(b_j1, b_j6)}
__device__ int4   g_edge[N_EDGES];
__device__ float  g_deg[N_NODES];
__device__ float4 g_agg[N_NODES * 4];            // [N][16]; zero at call entry/exit
__device__ float4 g_h1[N_NODES * 4];             // hidden ping
__device__ float4 g_h2[N_NODES * 4];             // hidden pong
__device__ uint2  g_xwh[N_NODES * 100];          // [N][25][16] fp16 XW (80MB, keep L2-hot)

// ---------------- kernels --------------------------------------------------

__global__ void zero_deg_kernel() {
    int i = blockIdx.x * blockDim.x + threadIdx.x;
    if (i < N_NODES) g_deg[i] = 0.f;
}

__global__ void prep_kernel(const float2* __restrict__ attr,
                            const int* __restrict__ src,
                            const int* __restrict__ dst) {
    int e = blockIdx.x * blockDim.x + threadIdx.x;
    if (e >= N_EDGES) return;
    float2 a = attr[e];
    float v0 = a.x * 4.f, v1 = a.y * 4.f;
    float k0f = fminf(fmaxf(floorf(v0), 0.f), 3.f);
    float k1f = fminf(fmaxf(floorf(v1), 0.f), 3.f);
    float f0 = v0 - k0f, f1 = v1 - k1f;
    int k0 = (int)k0f, k1 = (int)k1f;
    float bj  = (1.f - f0) * (1.f - f1);
    float bj5 = (1.f - f0) * f1;
    float bj1 = f0 * (1.f - f1);
    float bj6 = f0 * f1;
    int j = k0 + 5 * k1;
    int d = dst[e];
    __half2 p0 = __floats2half2_rn(bj,  bj5);
    __half2 p1 = __floats2half2_rn(bj1, bj6);
    int4 rec;
    rec.x = src[e] | (j << 20);
    rec.y = d;
    rec.z = *reinterpret_cast<int*>(&p0);
    rec.w = *reinterpret_cast<int*>(&p1);
    __stcs(&g_edge[e], rec);                     // streaming store: don't pollute L2
    atomicAdd(&g_deg[d], 1.f);
}

__device__ __forceinline__ void red_add_v4(float* p, float4 v) {
    asm volatile("red.global.add.v4.f32 [%0], {%1,%2,%3,%4};"
                 :: "l"(p), "f"(v.x), "f"(v.y), "f"(v.z), "f"(v.w) : "memory");
}

__device__ __forceinline__ float2 h2f2(unsigned u) {
    __half2 h = *reinterpret_cast<__half2*>(&u);
    return __half22float2(h);
}

// Layer 1 edge kernel: in=2, 4 threads/edge, TWO edges per thread (MLP).
__global__ void edge1_kernel(const float2* __restrict__ x,
                             const float* __restrict__ W1) {
    __shared__ uint4 Wsh[100];                   // [25][4] fp16
    if (threadIdx.x < 100) {
        int w = threadIdx.x >> 2, l = threadIdx.x & 3;
        const float4* Wv = (const float4*)W1;    // [25][2][4] float4
        float4 a0 = Wv[w * 8 + l];
        float4 a1 = Wv[w * 8 + 4 + l];
        __half2 p0 = __floats2half2_rn(a0.x, a0.y);
        __half2 p1 = __floats2half2_rn(a0.z, a0.w);
        __half2 p2 = __floats2half2_rn(a1.x, a1.y);
        __half2 p3 = __floats2half2_rn(a1.z, a1.w);
        uint4 u;
        u.x = *reinterpret_cast<unsigned*>(&p0);
        u.y = *reinterpret_cast<unsigned*>(&p1);
        u.z = *reinterpret_cast<unsigned*>(&p2);
        u.w = *reinterpret_cast<unsigned*>(&p3);
        Wsh[w * 4 + l] = u;
    }
    __syncthreads();
    int t = blockIdx.x * blockDim.x + threadIdx.x;   // HALF_E*4 threads
    int eA = t >> 2;
    int eB = eA + HALF_E;
    int l = threadIdx.x & 3;
    // front-batch both edge records (streaming) and both x gathers (MLP=4)
    int4 recA = __ldcs(&g_edge[eA]);
    int4 recB = __ldcs(&g_edge[eB]);
    int sA = recA.x & 0xFFFFF, jA = recA.x >> 20;
    int sB = recB.x & 0xFFFFF, jB = recB.x >> 20;
    float2 xvA = x[sA];
    float2 xvB = x[sB];
    const int woff[4] = {0, 5, 1, 6};
    {
        float2 b0 = h2f2(recA.z), b1 = h2f2(recA.w);
        float bs[4] = {b0.x, b0.y, b1.x, b1.y};
        float4 acc = make_float4(0.f, 0.f, 0.f, 0.f);
#pragma unroll
        for (int q = 0; q < 4; q++) {
            uint4 wv = Wsh[(jA + woff[q]) * 4 + l];
            float2 w00 = h2f2(wv.x), w01 = h2f2(wv.y);
            float2 w10 = h2f2(wv.z), w11 = h2f2(wv.w);
            float c0 = bs[q] * xvA.x, c1 = bs[q] * xvA.y;
            acc.x += c0 * w00.x + c1 * w10.x;
            acc.y += c0 * w00.y + c1 * w10.y;
            acc.z += c0 * w01.x + c1 * w11.x;
            acc.w += c0 * w01.y + c1 * w11.y;
        }
        red_add_v4((float*)&g_agg[(size_t)recA.y * 4 + l], acc);
    }
    {
        float2 b0 = h2f2(recB.z), b1 = h2f2(recB.w);
        float bs[4] = {b0.x, b0.y, b1.x, b1.y};
        float4 acc = make_float4(0.f, 0.f, 0.f, 0.f);
#pragma unroll
        for (int q = 0; q < 4; q++) {
            uint4 wv = Wsh[(jB + woff[q]) * 4 + l];
            float2 w00 = h2f2(wv.x), w01 = h2f2(wv.y);
            float2 w10 = h2f2(wv.z), w11 = h2f2(wv.w);
            float c0 = bs[q] * xvB.x, c1 = bs[q] * xvB.y;
            acc.x += c0 * w00.x + c1 * w10.x;
            acc.y += c0 * w00.y + c1 * w10.y;
            acc.z += c0 * w01.x + c1 * w11.x;
            acc.w += c0 * w01.y + c1 * w11.y;
        }
        red_add_v4((float*)&g_agg[(size_t)recB.y * 4 + l], acc);
    }
}

// XW precompute: 128 threads, 100 active as (k,o4), fp16 output.
__global__ void xw_kernel(const float4* __restrict__ hin,
                          const float* __restrict__ W) {
    __shared__ float4 hs[400];                   // 100 nodes x 16 floats
    int t = threadIdx.x;
    int n0 = blockIdx.x * 100;
    int k = t >> 2, o4 = t & 3;
    float4 wc[16];
    if (t < 100) {
        const float4* Wv = (const float4*)W;     // [25][16][4]
#pragma unroll
        for (int i = 0; i < 16; i++) wc[i] = Wv[(k * 16 + i) * 4 + o4];
    }
    for (int j = t; j < 400; j += blockDim.x) hs[j] = hin[n0 * 4 + j];
    __syncthreads();
    if (t >= 100) return;
    const float* hsf = (const float*)hs;
    for (int n = 0; n < 100; n++) {
        float4 a = make_float4(0.f, 0.f, 0.f, 0.f);
#pragma unroll
        for (int i = 0; i < 16; i++) {
            float hv = hsf[n * 16 + i];
            a.x += hv * wc[i].x; a.y += hv * wc[i].y;
            a.z += hv * wc[i].z; a.w += hv * wc[i].w;
        }
        __half2 h0 = __floats2half2_rn(a.x, a.y);
        __half2 h1 = __floats2half2_rn(a.z, a.w);
        uint2 u;
        u.x = *reinterpret_cast<unsigned*>(&h0);
        u.y = *reinterpret_cast<unsigned*>(&h1);
        g_xwh[((size_t)(n0 + n) * 25 + k) * 4 + o4] = u;
    }
}

// Edge gather for layers 2/3: 4 threads/edge, TWO edges per thread.
// Edge records loaded evict-first so the 80MB XW table stays L2-resident.
__global__ void edge_gather_kernel() {
    int t = blockIdx.x * blockDim.x + threadIdx.x;
    int eA = t >> 2;
    int eB = eA + HALF_E;
    int l = threadIdx.x & 3;
    int4 recA = __ldcs(&g_edge[eA]);
    int4 recB = __ldcs(&g_edge[eB]);
    int sA = recA.x & 0xFFFFF, jA = recA.x >> 20;
    int sB = recB.x & 0xFFFFF, jB = recB.x >> 20;
    const char* baseA = (const char*)g_xwh + (size_t)sA * 800 + l * 16;
    const char* baseB = (const char*)g_xwh + (size_t)sB * 800 + l * 16;
    // front-batch all 4 tap-pair loads
    uint4 vA1 = *reinterpret_cast<const uint4*>(baseA + jA * 32);
    uint4 vA2 = *reinterpret_cast<const uint4*>(baseA + (jA + 5) * 32);
    uint4 vB1 = *reinterpret_cast<const uint4*>(baseB + jB * 32);
    uint4 vB2 = *reinterpret_cast<const uint4*>(baseB + (jB + 5) * 32);
    {
        float2 b0 = h2f2(recA.z), b1 = h2f2(recA.w);
        float cA = (l & 2) ? b1.x : b0.x;
        float cB = (l & 2) ? b1.y : b0.y;
        float acc[8];
        const unsigned* u1 = reinterpret_cast<const unsigned*>(&vA1);
        const unsigned* u2 = reinterpret_cast<const unsigned*>(&vA2);
#pragma unroll
        for (int i = 0; i < 4; i++) {
            float2 f1 = h2f2(u1[i]);
            float2 f2 = h2f2(u2[i]);
            acc[2 * i]     = cA * f1.x + cB * f2.x;
            acc[2 * i + 1] = cA * f1.y + cB * f2.y;
        }
#pragma unroll
        for (int i = 0; i < 8; i++)
            acc[i] += __shfl_xor_sync(FULL, acc[i], 2);
        float* ap = (float*)g_agg + (size_t)recA.y * 16 + ((l & 1) << 3) + ((l & 2) << 1);
        float4 out = (l & 2) ? make_float4(acc[4], acc[5], acc[6], acc[7])
                             : make_float4(acc[0], acc[1], acc[2], acc[3]);
        red_add_v4(ap, out);
    }
    {
        float2 b0 = h2f2(recB.z), b1 = h2f2(recB.w);
        float cA = (l & 2) ? b1.x : b0.x;
        float cB = (l & 2) ? b1.y : b0.y;
        float acc[8];
        const unsigned* u1 = reinterpret_cast<const unsigned*>(&vB1);
        const unsigned* u2 = reinterpret_cast<const unsigned*>(&vB2);
#pragma unroll
        for (int i = 0; i < 4; i++) {
            float2 f1 = h2f2(u1[i]);
            float2 f2 = h2f2(u2[i]);
            acc[2 * i]     = cA * f1.x + cB * f2.x;
            acc[2 * i + 1] = cA * f1.y + cB * f2.y;
        }
#pragma unroll
        for (int i = 0; i < 8; i++)
            acc[i] += __shfl_xor_sync(FULL, acc[i], 2);
        float* ap = (float*)g_agg + (size_t)recB.y * 16 + ((l & 1) << 3) + ((l & 2) << 1);
        float4 out = (l & 2) ? make_float4(acc[4], acc[5], acc[6], acc[7])
                             : make_float4(acc[0], acc[1], acc[2], acc[3]);
        red_add_v4(ap, out);
    }
}

// Node update, layer 1 (root: 2x16): h = relu(agg/deg + x@root + b); zero agg.
__global__ void node1_kernel(const float2* __restrict__ x,
                             const float* __restrict__ root,
                             const float* __restrict__ bias,
                             float4* __restrict__ hout) {
    __shared__ float4 rsh[8];
    __shared__ float4 bsh[4];
    if (threadIdx.x < 8)  rsh[threadIdx.x] = ((const float4*)root)[threadIdx.x];
    if (threadIdx.x < 4)  bsh[threadIdx.x] = ((const float4*)bias)[threadIdx.x];
    __syncthreads();
    int t = blockIdx.x * blockDim.x + threadIdx.x;
    int n = t >> 2;
    if (n >= N_NODES) return;
    int l = t & 3;
    float4 a = g_agg[(size_t)n * 4 + l];
    float di = 1.f / fmaxf(g_deg[n], 1.f);
    float2 xv = x[n];
    float4 r0 = rsh[l], r1 = rsh[4 + l], bb = bsh[l];
    float4 o;
    o.x = fmaxf(bb.x + a.x * di + xv.x * r0.x + xv.y * r1.x, 0.f);
    o.y = fmaxf(bb.y + a.y * di + xv.x * r0.y + xv.y * r1.y, 0.f);
    o.z = fmaxf(bb.z + a.z * di + xv.x * r0.z + xv.y * r1.z, 0.f);
    o.w = fmaxf(bb.w + a.w * di + xv.x * r0.w + xv.y * r1.w, 0.f);
    hout[(size_t)n * 4 + l] = o;
    g_agg[(size_t)n * 4 + l] = make_float4(0.f, 0.f, 0.f, 0.f);
}

// Node update, 16-channel root; 4 threads/node.
__global__ void node16_kernel(const float4* __restrict__ hin,
                              const float* __restrict__ root,
                              const float* __restrict__ bias,
                              float4* __restrict__ hout) {
    __shared__ float4 rsh[64];                   // [16][4]
    __shared__ float4 bsh[4];
    for (int j = threadIdx.x; j < 64; j += blockDim.x)
        rsh[j] = ((const float4*)root)[j];
    if (threadIdx.x < 4) bsh[threadIdx.x] = ((const float4*)bias)[threadIdx.x];
    __syncthreads();
    int t = blockIdx.x * blockDim.x + threadIdx.x;
    int n = t >> 2;
    if (n >= N_NODES) return;
    int l = t & 3;
    float4 a = g_agg[(size_t)n * 4 + l];
    float di = 1.f / fmaxf(g_deg[n], 1.f);
    float4 acc = bsh[l];
    acc.x += a.x * di; acc.y += a.y * di; acc.z += a.z * di; acc.w += a.w * di;
    const float* h = (const float*)(hin + (size_t)n * 4);
#pragma unroll
    for (int i = 0; i < 16; i++) {
        float hv = h[i];
        float4 r = rsh[i * 4 + l];
        acc.x += hv * r.x; acc.y += hv * r.y; acc.z += hv * r.z; acc.w += hv * r.w;
    }
    acc.x = fmaxf(acc.x, 0.f); acc.y = fmaxf(acc.y, 0.f);
    acc.z = fmaxf(acc.z, 0.f); acc.w = fmaxf(acc.w, 0.f);
    hout[(size_t)n * 4 + l] = acc;
    g_agg[(size_t)n * 4 + l] = make_float4(0.f, 0.f, 0.f, 0.f);
}

// Layer-3 node update fused with fc head: relu(...) -> dot fc_w -> sigmoid.
__global__ void node16_final_kernel(const float4* __restrict__ hin,
                                    const float* __restrict__ root,
                                    const float* __restrict__ bias,
                                    const float* __restrict__ fcw,
                                    const float* __restrict__ fcb,
                                    float* __restrict__ out) {
    __shared__ float4 rsh[64];
    __shared__ float4 bsh[4];
    __shared__ float4 wsh[4];
    for (int j = threadIdx.x; j < 64; j += blockDim.x)
        rsh[j] = ((const float4*)root)[j];
    if (threadIdx.x < 4) {
        bsh[threadIdx.x] = ((const float4*)bias)[threadIdx.x];
        wsh[threadIdx.x] = ((const float4*)fcw)[threadIdx.x];
    }
    __syncthreads();
    int t = blockIdx.x * blockDim.x + threadIdx.x;
    int n = t >> 2;
    if (n >= N_NODES) return;
    int l = t & 3;
    float4 a = g_agg[(size_t)n * 4 + l];
    float di = 1.f / fmaxf(g_deg[n], 1.f);
    float4 acc = bsh[l];
    acc.x += a.x * di; acc.y += a.y * di; acc.z += a.z * di; acc.w += a.w * di;
    const float* h = (const float*)(hin + (size_t)n * 4);
#pragma unroll
    for (int i = 0; i < 16; i++) {
        float hv = h[i];
        float4 r = rsh[i * 4 + l];
        acc.x += hv * r.x; acc.y += hv * r.y; acc.z += hv * r.z; acc.w += hv * r.w;
    }
    acc.x = fmaxf(acc.x, 0.f); acc.y = fmaxf(acc.y, 0.f);
    acc.z = fmaxf(acc.z, 0.f); acc.w = fmaxf(acc.w, 0.f);
    g_agg[(size_t)n * 4 + l] = make_float4(0.f, 0.f, 0.f, 0.f);
    float4 wv = wsh[l];
    float z = acc.x * wv.x + acc.y * wv.y + acc.z * wv.z + acc.w * wv.w;
    z += __shfl_xor_sync(FULL, z, 1);
    z += __shfl_xor_sync(FULL, z, 2);
    if (l == 0) out[n] = 1.f / (1.f + expf(-(z + fcb[0])));
}

// ---------------- launch ---------------------------------------------------

extern "C" void kernel_launch(void* const* d_in, const int* in_sizes, int n_in,
                              void* d_out, int out_size) {
    const float2* x     = (const float2*)d_in[0];
    const int*    ei    = (const int*)d_in[1];
    const float2* attr  = (const float2*)d_in[2];
    const float*  W1    = (const float*)d_in[3];
    const float*  root1 = (const float*)d_in[4];
    const float*  b1    = (const float*)d_in[5];
    const float*  W2    = (const float*)d_in[6];
    const float*  root2 = (const float*)d_in[7];
    const float*  b2    = (const float*)d_in[8];
    const float*  W3    = (const float*)d_in[9];
    const float*  root3 = (const float*)d_in[10];
    const float*  b3    = (const float*)d_in[11];
    const float*  fcw   = (const float*)d_in[12];
    const float*  fcb   = (const float*)d_in[13];
    const int* src = ei;
    const int* dst = ei + N_EDGES;

    float4 *h1, *h2;
    cudaGetSymbolAddress((void**)&h1, g_h1);
    cudaGetSymbolAddress((void**)&h2, g_h2);

    const int TB = 256;
    int gEdge  = (N_EDGES + TB - 1) / TB;
    int gEdge2 = (HALF_E * 4) / TB;              // 2 edges/thread: 12500
    int gNode4 = (N_NODES * 4 + TB - 1) / TB;
    int gNode  = (N_NODES + TB - 1) / TB;

    zero_deg_kernel<<<gNode, TB>>>();
    prep_kernel<<<gEdge, TB>>>(attr, src, dst);

    // layer 1 (in=2)
    edge1_kernel<<<gEdge2, TB>>>(x, W1);
    node1_kernel<<<gNode4, TB>>>(x, root1, b1, h1);

    // layer 2
    xw_kernel<<<N_NODES / 100, 128>>>(h1, W2);
    edge_gather_kernel<<<gEdge2, TB>>>();
    node16_kernel<<<gNode4, TB>>>(h1, root2, b2, h2);

    // layer 3 (node update fused with fc head)
    xw_kernel<<<N_NODES / 100, 128>>>(h2, W3);
    edge_gather_kernel<<<gEdge2, TB>>>();
    node16_final_kernel<<<gNode4, TB>>>(h2, root3, b3, fcw, fcb, (float*)d_out);
}

// round 12
// speedup vs baseline: 1.0427x; 1.0178x over previous
#include <cuda_runtime.h>
#include <cuda_fp16.h>
#include <math.h>

#define N_NODES 100000
#define N_EDGES 1600000
#define HALF_E  (N_EDGES / 2)
#define FULL 0xffffffffu

// ---------------- scratch (static device globals; no allocations) ----------
// Edge record: {src | j<<20, dst, half2(b_j, b_j5), half2(b_j1, b_j6)}
__device__ int4   g_edge[N_EDGES];
__device__ float  g_deg[N_NODES];
__device__ float4 g_agg[N_NODES * 4];            // [N][16]; zero at call entry/exit
__device__ float4 g_h1[N_NODES * 4];             // hidden ping
__device__ float4 g_h2[N_NODES * 4];             // hidden pong
__device__ uint2  g_xwh[N_NODES * 100];          // [N][25][16] fp16 XW (80MB, L2-hot)

// ---------------- kernels --------------------------------------------------

__global__ void zero_deg_kernel() {
    int i = blockIdx.x * blockDim.x + threadIdx.x;
    if (i < N_NODES) g_deg[i] = 0.f;
}

__device__ __forceinline__ void red_add_v4(float* p, float4 v) {
    asm volatile("red.global.add.v4.f32 [%0], {%1,%2,%3,%4};"
                 :: "l"(p), "f"(v.x), "f"(v.y), "f"(v.z), "f"(v.w) : "memory");
}

__device__ __forceinline__ float2 h2f2(unsigned u) {
    __half2 h = *reinterpret_cast<__half2*>(&u);
    return __half22float2(h);
}

// Fused prep + layer-1 edge kernel. 4 threads/edge, 2 edges/thread.
// Each lane redundantly decodes the tiny per-edge inputs (same L1 sectors),
// builds the 16B record in registers (stored component-wise, coalesced,
// streaming), does the deg count (lane 0), then runs the layer-1 tap math
// with W1 in shared (fp16) and reduces into agg.
__global__ void prep_edge1_kernel(const float2* __restrict__ attr,
                                  const int* __restrict__ src,
                                  const int* __restrict__ dst,
                                  const float2* __restrict__ x,
                                  const float* __restrict__ W1) {
    __shared__ uint4 Wsh[100];                   // [25][4] fp16
    if (threadIdx.x < 100) {
        int w = threadIdx.x >> 2, l = threadIdx.x & 3;
        const float4* Wv = (const float4*)W1;    // [25][2][4] float4
        float4 a0 = Wv[w * 8 + l];
        float4 a1 = Wv[w * 8 + 4 + l];
        __half2 p0 = __floats2half2_rn(a0.x, a0.y);
        __half2 p1 = __floats2half2_rn(a0.z, a0.w);
        __half2 p2 = __floats2half2_rn(a1.x, a1.y);
        __half2 p3 = __floats2half2_rn(a1.z, a1.w);
        uint4 u;
        u.x = *reinterpret_cast<unsigned*>(&p0);
        u.y = *reinterpret_cast<unsigned*>(&p1);
        u.z = *reinterpret_cast<unsigned*>(&p2);
        u.w = *reinterpret_cast<unsigned*>(&p3);
        Wsh[w * 4 + l] = u;
    }
    __syncthreads();
    int t = blockIdx.x * blockDim.x + threadIdx.x;   // HALF_E*4 threads
    int l = threadIdx.x & 3;
    const int woff[4] = {0, 5, 1, 6};
#pragma unroll
    for (int half = 0; half < 2; half++) {
        int e = (t >> 2) + half * HALF_E;
        // --- prep part (redundant across the quad; same sectors) ---
        float2 a = __ldcs(&attr[e]);
        int s = __ldcs(&src[e]);
        int d = __ldcs(&dst[e]);
        float v0 = a.x * 4.f, v1 = a.y * 4.f;
        float k0f = fminf(fmaxf(floorf(v0), 0.f), 3.f);
        float k1f = fminf(fmaxf(floorf(v1), 0.f), 3.f);
        float f0 = v0 - k0f, f1 = v1 - k1f;
        int j = (int)k0f + 5 * (int)k1f;
        float bj  = (1.f - f0) * (1.f - f1);
        float bj5 = (1.f - f0) * f1;
        float bj1 = f0 * (1.f - f1);
        float bj6 = f0 * f1;
        __half2 p0 = __floats2half2_rn(bj,  bj5);
        __half2 p1 = __floats2half2_rn(bj1, bj6);
        int rx = s | (j << 20);
        int rz = *reinterpret_cast<int*>(&p0);
        int rw = *reinterpret_cast<int*>(&p1);
        // component-wise record store: thread t writes word l -> coalesced
        int comp = (l == 0) ? rx : (l == 1) ? d : (l == 2) ? rz : rw;
        __stcs(&((int*)g_edge)[(size_t)e * 4 + l], comp);
        if (l == 0) atomicAdd(&g_deg[d], 1.f);
        // --- layer-1 edge math ---
        float2 xv = x[s];
        float bs[4] = {bj, bj5, bj1, bj6};
        float4 acc = make_float4(0.f, 0.f, 0.f, 0.f);
#pragma unroll
        for (int q = 0; q < 4; q++) {
            uint4 wv = Wsh[(j + woff[q]) * 4 + l];
            float2 w00 = h2f2(wv.x), w01 = h2f2(wv.y);
            float2 w10 = h2f2(wv.z), w11 = h2f2(wv.w);
            float c0 = bs[q] * xv.x, c1 = bs[q] * xv.y;
            acc.x += c0 * w00.x + c1 * w10.x;
            acc.y += c0 * w00.y + c1 * w10.y;
            acc.z += c0 * w01.x + c1 * w11.x;
            acc.w += c0 * w01.y + c1 * w11.y;
        }
        red_add_v4((float*)&g_agg[(size_t)d * 4 + l], acc);
    }
}

// XW precompute: 128 threads, 100 active as (k,o4), fp16 output.
__global__ void xw_kernel(const float4* __restrict__ hin,
                          const float* __restrict__ W) {
    __shared__ float4 hs[400];                   // 100 nodes x 16 floats
    int t = threadIdx.x;
    int n0 = blockIdx.x * 100;
    int k = t >> 2, o4 = t & 3;
    float4 wc[16];
    if (t < 100) {
        const float4* Wv = (const float4*)W;     // [25][16][4]
#pragma unroll
        for (int i = 0; i < 16; i++) wc[i] = Wv[(k * 16 + i) * 4 + o4];
    }
    for (int j = t; j < 400; j += blockDim.x) hs[j] = hin[n0 * 4 + j];
    __syncthreads();
    if (t >= 100) return;
    const float* hsf = (const float*)hs;
    for (int n = 0; n < 100; n++) {
        float4 a = make_float4(0.f, 0.f, 0.f, 0.f);
#pragma unroll
        for (int i = 0; i < 16; i++) {
            float hv = hsf[n * 16 + i];
            a.x += hv * wc[i].x; a.y += hv * wc[i].y;
            a.z += hv * wc[i].z; a.w += hv * wc[i].w;
        }
        __half2 h0 = __floats2half2_rn(a.x, a.y);
        __half2 h1 = __floats2half2_rn(a.z, a.w);
        uint2 u;
        u.x = *reinterpret_cast<unsigned*>(&h0);
        u.y = *reinterpret_cast<unsigned*>(&h1);
        g_xwh[((size_t)(n0 + n) * 25 + k) * 4 + o4] = u;
    }
}

// Edge gather for layers 2/3: 4 threads/edge, TWO edges per thread.
__global__ void edge_gather_kernel() {
    int t = blockIdx.x * blockDim.x + threadIdx.x;
    int eA = t >> 2;
    int eB = eA + HALF_E;
    int l = threadIdx.x & 3;
    int4 recA = __ldcs(&g_edge[eA]);
    int4 recB = __ldcs(&g_edge[eB]);
    int sA = recA.x & 0xFFFFF, jA = recA.x >> 20;
    int sB = recB.x & 0xFFFFF, jB = recB.x >> 20;
    const char* baseA = (const char*)g_xwh + (size_t)sA * 800 + l * 16;
    const char* baseB = (const char*)g_xwh + (size_t)sB * 800 + l * 16;
    uint4 vA1 = *reinterpret_cast<const uint4*>(baseA + jA * 32);
    uint4 vA2 = *reinterpret_cast<const uint4*>(baseA + (jA + 5) * 32);
    uint4 vB1 = *reinterpret_cast<const uint4*>(baseB + jB * 32);
    uint4 vB2 = *reinterpret_cast<const uint4*>(baseB + (jB + 5) * 32);
    {
        float2 b0 = h2f2(recA.z), b1 = h2f2(recA.w);
        float cA = (l & 2) ? b1.x : b0.x;
        float cB = (l & 2) ? b1.y : b0.y;
        float acc[8];
        const unsigned* u1 = reinterpret_cast<const unsigned*>(&vA1);
        const unsigned* u2 = reinterpret_cast<const unsigned*>(&vA2);
#pragma unroll
        for (int i = 0; i < 4; i++) {
            float2 f1 = h2f2(u1[i]);
            float2 f2 = h2f2(u2[i]);
            acc[2 * i]     = cA * f1.x + cB * f2.x;
            acc[2 * i + 1] = cA * f1.y + cB * f2.y;
        }
#pragma unroll
        for (int i = 0; i < 8; i++)
            acc[i] += __shfl_xor_sync(FULL, acc[i], 2);
        float* ap = (float*)g_agg + (size_t)recA.y * 16 + ((l & 1) << 3) + ((l & 2) << 1);
        float4 out = (l & 2) ? make_float4(acc[4], acc[5], acc[6], acc[7])
                             : make_float4(acc[0], acc[1], acc[2], acc[3]);
        red_add_v4(ap, out);
    }
    {
        float2 b0 = h2f2(recB.z), b1 = h2f2(recB.w);
        float cA = (l & 2) ? b1.x : b0.x;
        float cB = (l & 2) ? b1.y : b0.y;
        float acc[8];
        const unsigned* u1 = reinterpret_cast<const unsigned*>(&vB1);
        const unsigned* u2 = reinterpret_cast<const unsigned*>(&vB2);
#pragma unroll
        for (int i = 0; i < 4; i++) {
            float2 f1 = h2f2(u1[i]);
            float2 f2 = h2f2(u2[i]);
            acc[2 * i]     = cA * f1.x + cB * f2.x;
            acc[2 * i + 1] = cA * f1.y + cB * f2.y;
        }
#pragma unroll
        for (int i = 0; i < 8; i++)
            acc[i] += __shfl_xor_sync(FULL, acc[i], 2);
        float* ap = (float*)g_agg + (size_t)recB.y * 16 + ((l & 1) << 3) + ((l & 2) << 1);
        float4 out = (l & 2) ? make_float4(acc[4], acc[5], acc[6], acc[7])
                             : make_float4(acc[0], acc[1], acc[2], acc[3]);
        red_add_v4(ap, out);
    }
}

// Node update, layer 1 (root: 2x16): h = relu(agg/deg + x@root + b); zero agg.
__global__ void node1_kernel(const float2* __restrict__ x,
                             const float* __restrict__ root,
                             const float* __restrict__ bias,
                             float4* __restrict__ hout) {
    __shared__ float4 rsh[8];
    __shared__ float4 bsh[4];
    if (threadIdx.x < 8)  rsh[threadIdx.x] = ((const float4*)root)[threadIdx.x];
    if (threadIdx.x < 4)  bsh[threadIdx.x] = ((const float4*)bias)[threadIdx.x];
    __syncthreads();
    int t = blockIdx.x * blockDim.x + threadIdx.x;
    int n = t >> 2;
    if (n >= N_NODES) return;
    int l = t & 3;
    float4 a = g_agg[(size_t)n * 4 + l];
    float di = 1.f / fmaxf(g_deg[n], 1.f);
    float2 xv = x[n];
    float4 r0 = rsh[l], r1 = rsh[4 + l], bb = bsh[l];
    float4 o;
    o.x = fmaxf(bb.x + a.x * di + xv.x * r0.x + xv.y * r1.x, 0.f);
    o.y = fmaxf(bb.y + a.y * di + xv.x * r0.y + xv.y * r1.y, 0.f);
    o.z = fmaxf(bb.z + a.z * di + xv.x * r0.z + xv.y * r1.z, 0.f);
    o.w = fmaxf(bb.w + a.w * di + xv.x * r0.w + xv.y * r1.w, 0.f);
    hout[(size_t)n * 4 + l] = o;
    g_agg[(size_t)n * 4 + l] = make_float4(0.f, 0.f, 0.f, 0.f);
}

// Node update, 16-channel root; 4 threads/node.
__global__ void node16_kernel(const float4* __restrict__ hin,
                              const float* __restrict__ root,
                              const float* __restrict__ bias,
                              float4* __restrict__ hout) {
    __shared__ float4 rsh[64];                   // [16][4]
    __shared__ float4 bsh[4];
    for (int j = threadIdx.x; j < 64; j += blockDim.x)
        rsh[j] = ((const float4*)root)[j];
    if (threadIdx.x < 4) bsh[threadIdx.x] = ((const float4*)bias)[threadIdx.x];
    __syncthreads();
    int t = blockIdx.x * blockDim.x + threadIdx.x;
    int n = t >> 2;
    if (n >= N_NODES) return;
    int l = t & 3;
    float4 a = g_agg[(size_t)n * 4 + l];
    float di = 1.f / fmaxf(g_deg[n], 1.f);
    float4 acc = bsh[l];
    acc.x += a.x * di; acc.y += a.y * di; acc.z += a.z * di; acc.w += a.w * di;
    const float* h = (const float*)(hin + (size_t)n * 4);
#pragma unroll
    for (int i = 0; i < 16; i++) {
        float hv = h[i];
        float4 r = rsh[i * 4 + l];
        acc.x += hv * r.x; acc.y += hv * r.y; acc.z += hv * r.z; acc.w += hv * r.w;
    }
    acc.x = fmaxf(acc.x, 0.f); acc.y = fmaxf(acc.y, 0.f);
    acc.z = fmaxf(acc.z, 0.f); acc.w = fmaxf(acc.w, 0.f);
    hout[(size_t)n * 4 + l] = acc;
    g_agg[(size_t)n * 4 + l] = make_float4(0.f, 0.f, 0.f, 0.f);
}

// Layer-3 node update fused with fc head: relu(...) -> dot fc_w -> sigmoid.
__global__ void node16_final_kernel(const float4* __restrict__ hin,
                                    const float* __restrict__ root,
                                    const float* __restrict__ bias,
                                    const float* __restrict__ fcw,
                                    const float* __restrict__ fcb,
                                    float* __restrict__ out) {
    __shared__ float4 rsh[64];
    __shared__ float4 bsh[4];
    __shared__ float4 wsh[4];
    for (int j = threadIdx.x; j < 64; j += blockDim.x)
        rsh[j] = ((const float4*)root)[j];
    if (threadIdx.x < 4) {
        bsh[threadIdx.x] = ((const float4*)bias)[threadIdx.x];
        wsh[threadIdx.x] = ((const float4*)fcw)[threadIdx.x];
    }
    __syncthreads();
    int t = blockIdx.x * blockDim.x + threadIdx.x;
    int n = t >> 2;
    if (n >= N_NODES) return;
    int l = t & 3;
    float4 a = g_agg[(size_t)n * 4 + l];
    float di = 1.f / fmaxf(g_deg[n], 1.f);
    float4 acc = bsh[l];
    acc.x += a.x * di; acc.y += a.y * di; acc.z += a.z * di; acc.w += a.w * di;
    const float* h = (const float*)(hin + (size_t)n * 4);
#pragma unroll
    for (int i = 0; i < 16; i++) {
        float hv = h[i];
        float4 r = rsh[i * 4 + l];
        acc.x += hv * r.x; acc.y += hv * r.y; acc.z += hv * r.z; acc.w += hv * r.w;
    }
    acc.x = fmaxf(acc.x, 0.f); acc.y = fmaxf(acc.y, 0.f);
    acc.z = fmaxf(acc.z, 0.f); acc.w = fmaxf(acc.w, 0.f);
    g_agg[(size_t)n * 4 + l] = make_float4(0.f, 0.f, 0.f, 0.f);
    float4 wv = wsh[l];
    float z = acc.x * wv.x + acc.y * wv.y + acc.z * wv.z + acc.w * wv.w;
    z += __shfl_xor_sync(FULL, z, 1);
    z += __shfl_xor_sync(FULL, z, 2);
    if (l == 0) out[n] = 1.f / (1.f + expf(-(z + fcb[0])));
}

// ---------------- launch ---------------------------------------------------

extern "C" void kernel_launch(void* const* d_in, const int* in_sizes, int n_in,
                              void* d_out, int out_size) {
    const float2* x     = (const float2*)d_in[0];
    const int*    ei    = (const int*)d_in[1];
    const float2* attr  = (const float2*)d_in[2];
    const float*  W1    = (const float*)d_in[3];
    const float*  root1 = (const float*)d_in[4];
    const float*  b1    = (const float*)d_in[5];
    const float*  W2    = (const float*)d_in[6];
    const float*  root2 = (const float*)d_in[7];
    const float*  b2    = (const float*)d_in[8];
    const float*  W3    = (const float*)d_in[9];
    const float*  root3 = (const float*)d_in[10];
    const float*  b3    = (const float*)d_in[11];
    const float*  fcw   = (const float*)d_in[12];
    const float*  fcb   = (const float*)d_in[13];
    const int* src = ei;
    const int* dst = ei + N_EDGES;

    float4 *h1, *h2;
    cudaGetSymbolAddress((void**)&h1, g_h1);
    cudaGetSymbolAddress((void**)&h2, g_h2);

    const int TB = 256;
    int gEdge2 = (HALF_E * 4) / TB;              // 2 edges/thread: 12500
    int gNode4 = (N_NODES * 4 + TB - 1) / TB;
    int gNode  = (N_NODES + TB - 1) / TB;

    zero_deg_kernel<<<gNode, TB>>>();

    // fused: prep + layer-1 edge phase
    prep_edge1_kernel<<<gEdge2, TB>>>(attr, src, dst, x, W1);
    node1_kernel<<<gNode4, TB>>>(x, root1, b1, h1);

    // layer 2
    xw_kernel<<<N_NODES / 100, 128>>>(h1, W2);
    edge_gather_kernel<<<gEdge2, TB>>>();
    node16_kernel<<<gNode4, TB>>>(h1, root2, b2, h2);

    // layer 3 (node update fused with fc head)
    xw_kernel<<<N_NODES / 100, 128>>>(h2, W3);
    edge_gather_kernel<<<gEdge2, TB>>>();
    node16_final_kernel<<<gNode4, TB>>>(h2, root3, b3, fcw, fcb, (float*)d_out);
}

// round 13
// speedup vs baseline: 1.0428x; 1.0001x over previous
#include <cuda_runtime.h>
#include <cuda_fp16.h>
#include <math.h>

#define N_NODES 100000
#define N_EDGES 1600000
#define HALF_E  (N_EDGES / 2)
#define FULL 0xffffffffu

// ---------------- scratch (static device globals; no allocations) ----------
// Edge record: {src | j<<20, dst, half2(b_j, b_j5), half2(b_j1, b_j6)}
__device__ int4   g_edge[N_EDGES];
__device__ float  g_deg[N_NODES];
__device__ float4 g_agg[N_NODES * 4];            // [N][16]; zero at call entry/exit
__device__ float4 g_h1[N_NODES * 4];             // hidden ping
__device__ float4 g_h2[N_NODES * 4];             // hidden pong
__device__ uint2  g_xwh[N_NODES * 100];          // [N][25][16] fp16 XW (80MB, L2-hot)

// ---------------- helpers ---------------------------------------------------

__device__ __forceinline__ void red_add_v4(float* p, float4 v) {
    asm volatile("red.global.add.v4.f32 [%0], {%1,%2,%3,%4};"
                 :: "l"(p), "f"(v.x), "f"(v.y), "f"(v.z), "f"(v.w) : "memory");
}

__device__ __forceinline__ float2 h2f2(unsigned u) {
    __half2 h = *reinterpret_cast<__half2*>(&u);
    return __half22float2(h);
}

__device__ __forceinline__ unsigned long long pack_f32x2(float lo, float hi) {
    unsigned long long d;
    asm("mov.b64 %0, {%1, %2};" : "=l"(d) : "f"(lo), "f"(hi));
    return d;
}

__device__ __forceinline__ void unpack_f32x2(float& lo, float& hi, unsigned long long v) {
    asm("mov.b64 {%0, %1}, %2;" : "=f"(lo), "=f"(hi) : "l"(v));
}

__device__ __forceinline__ void fma_f32x2(unsigned long long& d,
                                          unsigned long long a,
                                          unsigned long long b,
                                          unsigned long long c) {
    asm("fma.rn.f32x2 %0, %1, %2, %3;" : "=l"(d) : "l"(a), "l"(b), "l"(c));
}

// ---------------- kernels --------------------------------------------------

__global__ void zero_deg_kernel() {
    int i = blockIdx.x * blockDim.x + threadIdx.x;
    if (i < N_NODES) g_deg[i] = 0.f;
}

// Fused prep + layer-1 edge kernel. 4 threads/edge, 2 edges/thread.
__global__ void prep_edge1_kernel(const float2* __restrict__ attr,
                                  const int* __restrict__ src,
                                  const int* __restrict__ dst,
                                  const float2* __restrict__ x,
                                  const float* __restrict__ W1) {
    __shared__ uint4 Wsh[100];                   // [25][4] fp16
    if (threadIdx.x < 100) {
        int w = threadIdx.x >> 2, l = threadIdx.x & 3;
        const float4* Wv = (const float4*)W1;    // [25][2][4] float4
        float4 a0 = Wv[w * 8 + l];
        float4 a1 = Wv[w * 8 + 4 + l];
        __half2 p0 = __floats2half2_rn(a0.x, a0.y);
        __half2 p1 = __floats2half2_rn(a0.z, a0.w);
        __half2 p2 = __floats2half2_rn(a1.x, a1.y);
        __half2 p3 = __floats2half2_rn(a1.z, a1.w);
        uint4 u;
        u.x = *reinterpret_cast<unsigned*>(&p0);
        u.y = *reinterpret_cast<unsigned*>(&p1);
        u.z = *reinterpret_cast<unsigned*>(&p2);
        u.w = *reinterpret_cast<unsigned*>(&p3);
        Wsh[w * 4 + l] = u;
    }
    __syncthreads();
    int t = blockIdx.x * blockDim.x + threadIdx.x;   // HALF_E*4 threads
    int l = threadIdx.x & 3;
    const int woff[4] = {0, 5, 1, 6};
#pragma unroll
    for (int half = 0; half < 2; half++) {
        int e = (t >> 2) + half * HALF_E;
        float2 a = __ldcs(&attr[e]);
        int s = __ldcs(&src[e]);
        int d = __ldcs(&dst[e]);
        float v0 = a.x * 4.f, v1 = a.y * 4.f;
        float k0f = fminf(fmaxf(floorf(v0), 0.f), 3.f);
        float k1f = fminf(fmaxf(floorf(v1), 0.f), 3.f);
        float f0 = v0 - k0f, f1 = v1 - k1f;
        int j = (int)k0f + 5 * (int)k1f;
        float bj  = (1.f - f0) * (1.f - f1);
        float bj5 = (1.f - f0) * f1;
        float bj1 = f0 * (1.f - f1);
        float bj6 = f0 * f1;
        __half2 p0 = __floats2half2_rn(bj,  bj5);
        __half2 p1 = __floats2half2_rn(bj1, bj6);
        int rx = s | (j << 20);
        int rz = *reinterpret_cast<int*>(&p0);
        int rw = *reinterpret_cast<int*>(&p1);
        int comp = (l == 0) ? rx : (l == 1) ? d : (l == 2) ? rz : rw;
        __stcs(&((int*)g_edge)[(size_t)e * 4 + l], comp);
        if (l == 0) atomicAdd(&g_deg[d], 1.f);
        float2 xv = x[s];
        float bs[4] = {bj, bj5, bj1, bj6};
        float4 acc = make_float4(0.f, 0.f, 0.f, 0.f);
#pragma unroll
        for (int q = 0; q < 4; q++) {
            uint4 wv = Wsh[(j + woff[q]) * 4 + l];
            float2 w00 = h2f2(wv.x), w01 = h2f2(wv.y);
            float2 w10 = h2f2(wv.z), w11 = h2f2(wv.w);
            float c0 = bs[q] * xv.x, c1 = bs[q] * xv.y;
            acc.x += c0 * w00.x + c1 * w10.x;
            acc.y += c0 * w00.y + c1 * w10.y;
            acc.z += c0 * w01.x + c1 * w11.x;
            acc.w += c0 * w01.y + c1 * w11.y;
        }
        red_add_v4((float*)&g_agg[(size_t)d * 4 + l], acc);
    }
}

// XW precompute with packed f32x2 FMA: thread (k,o4) owns W[k][:][4o4..4o4+3]
// packed over input pairs (32 u64 regs). Per node: 8 LDS.64 broadcast +
// 32 FFMA2 (vs 16 LDS + 64 FFMA scalar) in an issue-bound kernel.
__global__ void xw_kernel(const float4* __restrict__ hin,
                          const float* __restrict__ W) {
    __shared__ float4 hs[400];                   // 100 nodes x 16 floats
    int t = threadIdx.x;
    int n0 = blockIdx.x * 100;
    int k = t >> 2, o4 = t & 3;
    unsigned long long wp[8][4];                 // [in-pair][out] packed {W[2p],W[2p+1]}
    if (t < 100) {
        const float4* Wv = (const float4*)W;     // [25][16][4]
#pragma unroll
        for (int p = 0; p < 8; p++) {
            float4 a = Wv[(k * 16 + 2 * p) * 4 + o4];
            float4 b = Wv[(k * 16 + 2 * p + 1) * 4 + o4];
            wp[p][0] = pack_f32x2(a.x, b.x);
            wp[p][1] = pack_f32x2(a.y, b.y);
            wp[p][2] = pack_f32x2(a.z, b.z);
            wp[p][3] = pack_f32x2(a.w, b.w);
        }
    }
    for (int j = t; j < 400; j += blockDim.x) hs[j] = hin[n0 * 4 + j];
    __syncthreads();
    if (t >= 100) return;
    const unsigned long long* hs64 = (const unsigned long long*)hs;  // {h[2p],h[2p+1]}
    for (int n = 0; n < 100; n++) {
        unsigned long long acc0 = 0ull, acc1 = 0ull, acc2 = 0ull, acc3 = 0ull;
#pragma unroll
        for (int p = 0; p < 8; p++) {
            unsigned long long hh = hs64[n * 8 + p];   // LDS.64 warp-broadcast
            fma_f32x2(acc0, hh, wp[p][0], acc0);
            fma_f32x2(acc1, hh, wp[p][1], acc1);
            fma_f32x2(acc2, hh, wp[p][2], acc2);
            fma_f32x2(acc3, hh, wp[p][3], acc3);
        }
        float lo, hi;
        float4 a;
        unpack_f32x2(lo, hi, acc0); a.x = lo + hi;
        unpack_f32x2(lo, hi, acc1); a.y = lo + hi;
        unpack_f32x2(lo, hi, acc2); a.z = lo + hi;
        unpack_f32x2(lo, hi, acc3); a.w = lo + hi;
        __half2 h0 = __floats2half2_rn(a.x, a.y);
        __half2 h1 = __floats2half2_rn(a.z, a.w);
        uint2 u;
        u.x = *reinterpret_cast<unsigned*>(&h0);
        u.y = *reinterpret_cast<unsigned*>(&h1);
        g_xwh[((size_t)(n0 + n) * 25 + k) * 4 + o4] = u;
    }
}

// Edge gather for layers 2/3: 4 threads/edge, TWO edges per thread.
__global__ void edge_gather_kernel() {
    int t = blockIdx.x * blockDim.x + threadIdx.x;
    int eA = t >> 2;
    int eB = eA + HALF_E;
    int l = threadIdx.x & 3;
    int4 recA = __ldcs(&g_edge[eA]);
    int4 recB = __ldcs(&g_edge[eB]);
    int sA = recA.x & 0xFFFFF, jA = recA.x >> 20;
    int sB = recB.x & 0xFFFFF, jB = recB.x >> 20;
    const char* baseA = (const char*)g_xwh + (size_t)sA * 800 + l * 16;
    const char* baseB = (const char*)g_xwh + (size_t)sB * 800 + l * 16;
    uint4 vA1 = *reinterpret_cast<const uint4*>(baseA + jA * 32);
    uint4 vA2 = *reinterpret_cast<const uint4*>(baseA + (jA + 5) * 32);
    uint4 vB1 = *reinterpret_cast<const uint4*>(baseB + jB * 32);
    uint4 vB2 = *reinterpret_cast<const uint4*>(baseB + (jB + 5) * 32);
    {
        float2 b0 = h2f2(recA.z), b1 = h2f2(recA.w);
        float cA = (l & 2) ? b1.x : b0.x;
        float cB = (l & 2) ? b1.y : b0.y;
        float acc[8];
        const unsigned* u1 = reinterpret_cast<const unsigned*>(&vA1);
        const unsigned* u2 = reinterpret_cast<const unsigned*>(&vA2);
#pragma unroll
        for (int i = 0; i < 4; i++) {
            float2 f1 = h2f2(u1[i]);
            float2 f2 = h2f2(u2[i]);
            acc[2 * i]     = cA * f1.x + cB * f2.x;
            acc[2 * i + 1] = cA * f1.y + cB * f2.y;
        }
#pragma unroll
        for (int i = 0; i < 8; i++)
            acc[i] += __shfl_xor_sync(FULL, acc[i], 2);
        float* ap = (float*)g_agg + (size_t)recA.y * 16 + ((l & 1) << 3) + ((l & 2) << 1);
        float4 out = (l & 2) ? make_float4(acc[4], acc[5], acc[6], acc[7])
                             : make_float4(acc[0], acc[1], acc[2], acc[3]);
        red_add_v4(ap, out);
    }
    {
        float2 b0 = h2f2(recB.z), b1 = h2f2(recB.w);
        float cA = (l & 2) ? b1.x : b0.x;
        float cB = (l & 2) ? b1.y : b0.y;
        float acc[8];
        const unsigned* u1 = reinterpret_cast<const unsigned*>(&vB1);
        const unsigned* u2 = reinterpret_cast<const unsigned*>(&vB2);
#pragma unroll
        for (int i = 0; i < 4; i++) {
            float2 f1 = h2f2(u1[i]);
            float2 f2 = h2f2(u2[i]);
            acc[2 * i]     = cA * f1.x + cB * f2.x;
            acc[2 * i + 1] = cA * f1.y + cB * f2.y;
        }
#pragma unroll
        for (int i = 0; i < 8; i++)
            acc[i] += __shfl_xor_sync(FULL, acc[i], 2);
        float* ap = (float*)g_agg + (size_t)recB.y * 16 + ((l & 1) << 3) + ((l & 2) << 1);
        float4 out = (l & 2) ? make_float4(acc[4], acc[5], acc[6], acc[7])
                             : make_float4(acc[0], acc[1], acc[2], acc[3]);
        red_add_v4(ap, out);
    }
}

// Node update, layer 1 (root: 2x16): h = relu(agg/deg + x@root + b); zero agg.
__global__ void node1_kernel(const float2* __restrict__ x,
                             const float* __restrict__ root,
                             const float* __restrict__ bias,
                             float4* __restrict__ hout) {
    __shared__ float4 rsh[8];
    __shared__ float4 bsh[4];
    if (threadIdx.x < 8)  rsh[threadIdx.x] = ((const float4*)root)[threadIdx.x];
    if (threadIdx.x < 4)  bsh[threadIdx.x] = ((const float4*)bias)[threadIdx.x];
    __syncthreads();
    int t = blockIdx.x * blockDim.x + threadIdx.x;
    int n = t >> 2;
    if (n >= N_NODES) return;
    int l = t & 3;
    float4 a = g_agg[(size_t)n * 4 + l];
    float di = 1.f / fmaxf(g_deg[n], 1.f);
    float2 xv = x[n];
    float4 r0 = rsh[l], r1 = rsh[4 + l], bb = bsh[l];
    float4 o;
    o.x = fmaxf(bb.x + a.x * di + xv.x * r0.x + xv.y * r1.x, 0.f);
    o.y = fmaxf(bb.y + a.y * di + xv.x * r0.y + xv.y * r1.y, 0.f);
    o.z = fmaxf(bb.z + a.z * di + xv.x * r0.z + xv.y * r1.z, 0.f);
    o.w = fmaxf(bb.w + a.w * di + xv.x * r0.w + xv.y * r1.w, 0.f);
    hout[(size_t)n * 4 + l] = o;
    g_agg[(size_t)n * 4 + l] = make_float4(0.f, 0.f, 0.f, 0.f);
}

// Node update, 16-channel root; 4 threads/node.
__global__ void node16_kernel(const float4* __restrict__ hin,
                              const float* __restrict__ root,
                              const float* __restrict__ bias,
                              float4* __restrict__ hout) {
    __shared__ float4 rsh[64];                   // [16][4]
    __shared__ float4 bsh[4];
    for (int j = threadIdx.x; j < 64; j += blockDim.x)
        rsh[j] = ((const float4*)root)[j];
    if (threadIdx.x < 4) bsh[threadIdx.x] = ((const float4*)bias)[threadIdx.x];
    __syncthreads();
    int t = blockIdx.x * blockDim.x + threadIdx.x;
    int n = t >> 2;
    if (n >= N_NODES) return;
    int l = t & 3;
    float4 a = g_agg[(size_t)n * 4 + l];
    float di = 1.f / fmaxf(g_deg[n], 1.f);
    float4 acc = bsh[l];
    acc.x += a.x * di; acc.y += a.y * di; acc.z += a.z * di; acc.w += a.w * di;
    const float* h = (const float*)(hin + (size_t)n * 4);
#pragma unroll
    for (int i = 0; i < 16; i++) {
        float hv = h[i];
        float4 r = rsh[i * 4 + l];
        acc.x += hv * r.x; acc.y += hv * r.y; acc.z += hv * r.z; acc.w += hv * r.w;
    }
    acc.x = fmaxf(acc.x, 0.f); acc.y = fmaxf(acc.y, 0.f);
    acc.z = fmaxf(acc.z, 0.f); acc.w = fmaxf(acc.w, 0.f);
    hout[(size_t)n * 4 + l] = acc;
    g_agg[(size_t)n * 4 + l] = make_float4(0.f, 0.f, 0.f, 0.f);
}

// Layer-3 node update fused with fc head: relu(...) -> dot fc_w -> sigmoid.
__global__ void node16_final_kernel(const float4* __restrict__ hin,
                                    const float* __restrict__ root,
                                    const float* __restrict__ bias,
                                    const float* __restrict__ fcw,
                                    const float* __restrict__ fcb,
                                    float* __restrict__ out) {
    __shared__ float4 rsh[64];
    __shared__ float4 bsh[4];
    __shared__ float4 wsh[4];
    for (int j = threadIdx.x; j < 64; j += blockDim.x)
        rsh[j] = ((const float4*)root)[j];
    if (threadIdx.x < 4) {
        bsh[threadIdx.x] = ((const float4*)bias)[threadIdx.x];
        wsh[threadIdx.x] = ((const float4*)fcw)[threadIdx.x];
    }
    __syncthreads();
    int t = blockIdx.x * blockDim.x + threadIdx.x;
    int n = t >> 2;
    if (n >= N_NODES) return;
    int l = t & 3;
    float4 a = g_agg[(size_t)n * 4 + l];
    float di = 1.f / fmaxf(g_deg[n], 1.f);
    float4 acc = bsh[l];
    acc.x += a.x * di; acc.y += a.y * di; acc.z += a.z * di; acc.w += a.w * di;
    const float* h = (const float*)(hin + (size_t)n * 4);
#pragma unroll
    for (int i = 0; i < 16; i++) {
        float hv = h[i];
        float4 r = rsh[i * 4 + l];
        acc.x += hv * r.x; acc.y += hv * r.y; acc.z += hv * r.z; acc.w += hv * r.w;
    }
    acc.x = fmaxf(acc.x, 0.f); acc.y = fmaxf(acc.y, 0.f);
    acc.z = fmaxf(acc.z, 0.f); acc.w = fmaxf(acc.w, 0.f);
    g_agg[(size_t)n * 4 + l] = make_float4(0.f, 0.f, 0.f, 0.f);
    float4 wv = wsh[l];
    float z = acc.x * wv.x + acc.y * wv.y + acc.z * wv.z + acc.w * wv.w;
    z += __shfl_xor_sync(FULL, z, 1);
    z += __shfl_xor_sync(FULL, z, 2);
    if (l == 0) out[n] = 1.f / (1.f + expf(-(z + fcb[0])));
}

// ---------------- launch ---------------------------------------------------

extern "C" void kernel_launch(void* const* d_in, const int* in_sizes, int n_in,
                              void* d_out, int out_size) {
    const float2* x     = (const float2*)d_in[0];
    const int*    ei    = (const int*)d_in[1];
    const float2* attr  = (const float2*)d_in[2];
    const float*  W1    = (const float*)d_in[3];
    const float*  root1 = (const float*)d_in[4];
    const float*  b1    = (const float*)d_in[5];
    const float*  W2    = (const float*)d_in[6];
    const float*  root2 = (const float*)d_in[7];
    const float*  b2    = (const float*)d_in[8];
    const float*  W3    = (const float*)d_in[9];
    const float*  root3 = (const float*)d_in[10];
    const float*  b3    = (const float*)d_in[11];
    const float*  fcw   = (const float*)d_in[12];
    const float*  fcb   = (const float*)d_in[13];
    const int* src = ei;
    const int* dst = ei + N_EDGES;

    float4 *h1, *h2;
    cudaGetSymbolAddress((void**)&h1, g_h1);
    cudaGetSymbolAddress((void**)&h2, g_h2);

    const int TB = 256;
    int gEdge2 = (HALF_E * 4) / TB;              // 2 edges/thread: 12500
    int gNode4 = (N_NODES * 4 + TB - 1) / TB;
    int gNode  = (N_NODES + TB - 1) / TB;

    zero_deg_kernel<<<gNode, TB>>>();

    // fused: prep + layer-1 edge phase
    prep_edge1_kernel<<<gEdge2, TB>>>(attr, src, dst, x, W1);
    node1_kernel<<<gNode4, TB>>>(x, root1, b1, h1);

    // layer 2
    xw_kernel<<<N_NODES / 100, 128>>>(h1, W2);
    edge_gather_kernel<<<gEdge2, TB>>>();
    node16_kernel<<<gNode4, TB>>>(h1, root2, b2, h2);

    // layer 3 (node update fused with fc head)
    xw_kernel<<<N_NODES / 100, 128>>>(h2, W3);
    edge_gather_kernel<<<gEdge2, TB>>>();
    node16_final_kernel<<<gNode4, TB>>>(h2, root3, b3, fcw, fcb, (float*)d_out);
}